// round 1
// baseline (speedup 1.0000x reference)
#include <cuda_runtime.h>

#define N_NODES 512
#define N_EDGES (512 * 512)

// ---------------- persistent device scratch (no allocations allowed) ---------
__device__ int   g_cnt[N_NODES];
__device__ int   g_ptr[N_NODES + 1];
__device__ int   g_off[N_NODES];
__device__ int   g_perm[N_EDGES];
__device__ float g_invc[N_NODES];
__device__ float g_bufA[N_NODES * 36];
__device__ float g_bufB[N_NODES * 36];

// ---------------- CSR build: histogram -> scan -> scatter --------------------
__global__ void zero_kernel() { g_cnt[threadIdx.x] = 0; }

__global__ void hist_kernel(const int* __restrict__ dst) {
    int e = blockIdx.x * blockDim.x + threadIdx.x;
    if (e < N_EDGES) atomicAdd(&g_cnt[dst[e]], 1);
}

__global__ void scan_kernel() {
    __shared__ int s[N_NODES];
    int t = threadIdx.x;
    int c = g_cnt[t];
    s[t] = c;
    __syncthreads();
    for (int off = 1; off < N_NODES; off <<= 1) {
        int v = (t >= off) ? s[t - off] : 0;
        __syncthreads();
        s[t] += v;
        __syncthreads();
    }
    g_ptr[t + 1] = s[t];
    if (t == 0) g_ptr[0] = 0;
    g_off[t]  = s[t] - c;                    // exclusive prefix = scatter base
    g_invc[t] = 1.0f / (float)max(c, 1);
}

__global__ void scatter_kernel(const int* __restrict__ dst) {
    int e = blockIdx.x * blockDim.x + threadIdx.x;
    if (e < N_EDGES) {
        int p = atomicAdd(&g_off[dst[e]], 1);
        g_perm[p] = e;
    }
}

// ---------------- NNConv layer: one CTA per dst node -------------------------
// msg_e[o] = sum_i x[src_e][i] * relu( sum_v ea[e][v]*We[v][i*COUT+o] + be[i*COUT+o] )
// h_out[d] = relu( mean_e(msg) + h_in[d] @ root + bias )
template <int CIN, int COUT>
__global__ __launch_bounds__(256) void layer_kernel(
    const float* __restrict__ ea,     // [E,6]
    const int*   __restrict__ srcv,   // [E]
    const float* __restrict__ We,     // [6, CIN*COUT]
    const float* __restrict__ be,     // [CIN*COUT]
    const float* __restrict__ root,   // [CIN, COUT]
    const float* __restrict__ bias,   // [COUT]
    const float* __restrict__ hin,    // [N, CIN]
    float*       __restrict__ hout)   // [N, COUT]
{
    constexpr int COUTP = (COUT + 3) & ~3;           // pad to float4
    __shared__ __align__(16) float sWe[6 * CIN * COUTP];
    __shared__ __align__(16) float sBe[CIN * COUTP];
    __shared__ float sacc[COUTP];

    const int tid = threadIdx.x;

    // stage weights (padded channel dim so LDS.128 works for any COUT)
    for (int t = tid; t < 6 * CIN * COUTP; t += 256) {
        int vi = t / COUTP, oc = t % COUTP;          // vi = v*CIN + i
        sWe[t] = (oc < COUT) ? We[vi * COUT + oc] : 0.f;
    }
    for (int t = tid; t < CIN * COUTP; t += 256) {
        int oc = t % COUTP;
        sBe[t] = (oc < COUT) ? be[(t / COUTP) * COUT + oc] : 0.f;
    }
    if (tid < COUTP) sacc[tid] = 0.f;
    __syncthreads();

    const int d = blockIdx.x;
    float msg[COUTP];
#pragma unroll
    for (int o = 0; o < COUTP; o++) msg[o] = 0.f;

    const int start = g_ptr[d], finish = g_ptr[d + 1];
    for (int k = start + tid; k < finish; k += 256) {
        const int e = g_perm[k];
        const int s = srcv[e];
        const float a0 = __ldg(ea + e * 6 + 0), a1 = __ldg(ea + e * 6 + 1),
                    a2 = __ldg(ea + e * 6 + 2), a3 = __ldg(ea + e * 6 + 3),
                    a4 = __ldg(ea + e * 6 + 4), a5 = __ldg(ea + e * 6 + 5);
        const float* xr = hin + s * CIN;
#pragma unroll 1   // keep i rolled: full unroll would blow the I$ for CIN=36
        for (int i = 0; i < CIN; i++) {
            const float xi = __ldg(xr + i);
            const float4* w0 = (const float4*)(sWe + (0 * CIN + i) * COUTP);
            const float4* w1 = (const float4*)(sWe + (1 * CIN + i) * COUTP);
            const float4* w2 = (const float4*)(sWe + (2 * CIN + i) * COUTP);
            const float4* w3 = (const float4*)(sWe + (3 * CIN + i) * COUTP);
            const float4* w4 = (const float4*)(sWe + (4 * CIN + i) * COUTP);
            const float4* w5 = (const float4*)(sWe + (5 * CIN + i) * COUTP);
            const float4* bb = (const float4*)(sBe + i * COUTP);
#pragma unroll
            for (int c = 0; c < COUTP / 4; c++) {
                const float4 b  = bb[c];
                const float4 v0 = w0[c], v1 = w1[c], v2 = w2[c],
                             v3 = w3[c], v4 = w4[c], v5 = w5[c];
                float t0 = fmaf(a0, v0.x, b.x); t0 = fmaf(a1, v1.x, t0);
                t0 = fmaf(a2, v2.x, t0); t0 = fmaf(a3, v3.x, t0);
                t0 = fmaf(a4, v4.x, t0); t0 = fmaf(a5, v5.x, t0);
                msg[c * 4 + 0] = fmaf(xi, fmaxf(t0, 0.f), msg[c * 4 + 0]);

                float t1 = fmaf(a0, v0.y, b.y); t1 = fmaf(a1, v1.y, t1);
                t1 = fmaf(a2, v2.y, t1); t1 = fmaf(a3, v3.y, t1);
                t1 = fmaf(a4, v4.y, t1); t1 = fmaf(a5, v5.y, t1);
                msg[c * 4 + 1] = fmaf(xi, fmaxf(t1, 0.f), msg[c * 4 + 1]);

                float t2 = fmaf(a0, v0.z, b.z); t2 = fmaf(a1, v1.z, t2);
                t2 = fmaf(a2, v2.z, t2); t2 = fmaf(a3, v3.z, t2);
                t2 = fmaf(a4, v4.z, t2); t2 = fmaf(a5, v5.z, t2);
                msg[c * 4 + 2] = fmaf(xi, fmaxf(t2, 0.f), msg[c * 4 + 2]);

                float t3 = fmaf(a0, v0.w, b.w); t3 = fmaf(a1, v1.w, t3);
                t3 = fmaf(a2, v2.w, t3); t3 = fmaf(a3, v3.w, t3);
                t3 = fmaf(a4, v4.w, t3); t3 = fmaf(a5, v5.w, t3);
                msg[c * 4 + 3] = fmaf(xi, fmaxf(t3, 0.f), msg[c * 4 + 3]);
            }
        }
    }

    // block reduction of per-thread msg -> sacc
#pragma unroll
    for (int o = 0; o < COUTP; o++) {
        float v = msg[o];
#pragma unroll
        for (int sh = 16; sh; sh >>= 1) v += __shfl_down_sync(0xffffffffu, v, sh);
        if ((tid & 31) == 0) atomicAdd(&sacc[o], v);
    }
    __syncthreads();

    // finalize: agg = sum/cnt; out = relu(agg + hin@root + bias)
    if (tid < COUT) {
        float r = bias[tid];
#pragma unroll 1
        for (int i = 0; i < CIN; i++)
            r = fmaf(hin[d * CIN + i], root[i * COUT + tid], r);
        hout[d * COUT + tid] = fmaxf(fmaf(sacc[tid], g_invc[d], r), 0.f);
    }
}

// ---------------- CBT: out[i][j] = sum_k |h[i][k]-h[j][k]|, k<5 --------------
__global__ __launch_bounds__(256) void cbt_kernel(const float* __restrict__ h,
                                                  float* __restrict__ out) {
    __shared__ float sh[N_NODES * 5];
    for (int t = threadIdx.x; t < N_NODES * 5; t += 256) sh[t] = h[t];
    __syncthreads();
    const int i = blockIdx.x;
    const float h0 = sh[i * 5 + 0], h1 = sh[i * 5 + 1], h2 = sh[i * 5 + 2],
                h3 = sh[i * 5 + 3], h4 = sh[i * 5 + 4];
    for (int j = threadIdx.x; j < N_NODES; j += 256) {
        float s = fabsf(h0 - sh[j * 5 + 0]) + fabsf(h1 - sh[j * 5 + 1]) +
                  fabsf(h2 - sh[j * 5 + 2]) + fabsf(h3 - sh[j * 5 + 3]) +
                  fabsf(h4 - sh[j * 5 + 4]);
        out[i * N_NODES + j] = s;
    }
}

// ---------------- launch ------------------------------------------------------
extern "C" void kernel_launch(void* const* d_in, const int* in_sizes, int n_in,
                              void* d_out, int out_size) {
    const float* x    = (const float*)d_in[0];
    const float* ea   = (const float*)d_in[1];
    const int*   ei   = (const int*)d_in[2];
    const float* We1  = (const float*)d_in[3];
    const float* be1  = (const float*)d_in[4];
    const float* root1= (const float*)d_in[5];
    const float* b1   = (const float*)d_in[6];
    const float* We2  = (const float*)d_in[7];
    const float* be2  = (const float*)d_in[8];
    const float* root2= (const float*)d_in[9];
    const float* b2   = (const float*)d_in[10];
    const float* We3  = (const float*)d_in[11];
    const float* be3  = (const float*)d_in[12];
    const float* root3= (const float*)d_in[13];
    const float* b3   = (const float*)d_in[14];
    float* out = (float*)d_out;

    const int* src = ei;
    const int* dst = ei + N_EDGES;

    float* hA = nullptr;
    float* hB = nullptr;
    cudaGetSymbolAddress((void**)&hA, g_bufA);
    cudaGetSymbolAddress((void**)&hB, g_bufB);

    // CSR build (per launch; deterministic work, order-nondeterministic perm is
    // numerically harmless under the 1e-3 tolerance)
    zero_kernel<<<1, N_NODES>>>();
    hist_kernel<<<N_EDGES / 256, 256>>>(dst);
    scan_kernel<<<1, N_NODES>>>();
    scatter_kernel<<<N_EDGES / 256, 256>>>(dst);

    layer_kernel<1, 36><<<N_NODES, 256>>>(ea, src, We1, be1, root1, b1, x,  hA);
    layer_kernel<36, 24><<<N_NODES, 256>>>(ea, src, We2, be2, root2, b2, hA, hB);
    layer_kernel<24, 5><<<N_NODES, 256>>>(ea, src, We3, be3, root3, b3, hB, hA);

    cbt_kernel<<<N_NODES, 256>>>(hA, out);
}

// round 2
// speedup vs baseline: 1.4892x; 1.4892x over previous
#include <cuda_runtime.h>
#include <cstdint>

#define N_NODES 512
#define N_EDGES (512 * 512)
#define CHUNKS 128
#define EDGES_PER_CHUNK (N_EDGES / CHUNKS)   // 2048

// ---------------- persistent device scratch (no allocations allowed) ---------
__device__ int   g_ptr[N_NODES + 1];
__device__ int   g_perm[N_EDGES];
__device__ float g_invc[N_NODES];
__device__ int   g_counts[CHUNKS * N_NODES];
__device__ int   g_base[CHUNKS * N_NODES];
__device__ float g_bufA[N_NODES * 36];
__device__ float g_bufB[N_NODES * 36];
__device__ float g_msg[(size_t)N_EDGES * 36];   // 37.75 MB msg buffer

// ---------------- f32x2 packed helpers ---------------------------------------
__device__ __forceinline__ uint64_t f2pk(float lo, float hi) {
    uint64_t r; asm("mov.b64 %0, {%1,%2};" : "=l"(r) : "f"(lo), "f"(hi)); return r;
}
__device__ __forceinline__ void f2upk(uint64_t v, float& lo, float& hi) {
    asm("mov.b64 {%0,%1}, %2;" : "=f"(lo), "=f"(hi) : "l"(v));
}
__device__ __forceinline__ uint64_t f2fma(uint64_t a, uint64_t b, uint64_t c) {
    uint64_t d; asm("fma.rn.f32x2 %0, %1, %2, %3;" : "=l"(d) : "l"(a), "l"(b), "l"(c));
    return d;
}
__device__ __forceinline__ uint64_t f2relu(uint64_t v) {
    float lo, hi; f2upk(v, lo, hi);
    return f2pk(fmaxf(lo, 0.f), fmaxf(hi, 0.f));
}

// ---------------- CSR build (atomic-free in gmem) ----------------------------
// A: per-chunk smem histograms
__global__ __launch_bounds__(256) void count_kernel(const int* __restrict__ dst) {
    __shared__ int h[N_NODES];
    for (int n = threadIdx.x; n < N_NODES; n += 256) h[n] = 0;
    __syncthreads();
    const int base = blockIdx.x * EDGES_PER_CHUNK;
    for (int k = threadIdx.x; k < EDGES_PER_CHUNK; k += 256)
        atomicAdd(&h[dst[base + k]], 1);
    __syncthreads();
    for (int n = threadIdx.x; n < N_NODES; n += 256)
        g_counts[blockIdx.x * N_NODES + n] = h[n];
}

// B: one CTA — column sums, node scan, per-(chunk,node) bases
__global__ __launch_bounds__(N_NODES) void plan_kernel() {
    __shared__ int s[N_NODES];
    const int t = threadIdx.x;
    int cnt = 0;
#pragma unroll 4
    for (int c = 0; c < CHUNKS; c++) cnt += g_counts[c * N_NODES + t];
    s[t] = cnt;
    __syncthreads();
    for (int off = 1; off < N_NODES; off <<= 1) {
        int v = (t >= off) ? s[t - off] : 0;
        __syncthreads();
        s[t] += v;
        __syncthreads();
    }
    const int incl = s[t];
    g_ptr[t + 1] = incl;
    if (t == 0) g_ptr[0] = 0;
    g_invc[t] = 1.0f / (float)max(cnt, 1);
    int run = incl - cnt;
#pragma unroll 4
    for (int c = 0; c < CHUNKS; c++) {
        int v = g_counts[c * N_NODES + t];
        g_base[c * N_NODES + t] = run;
        run += v;
    }
}

// C: scatter with smem cursors (no gmem atomics)
__global__ __launch_bounds__(256) void scatter_kernel(const int* __restrict__ dst) {
    __shared__ int cur[N_NODES];
    for (int n = threadIdx.x; n < N_NODES; n += 256)
        cur[n] = g_base[blockIdx.x * N_NODES + n];
    __syncthreads();
    const int base = blockIdx.x * EDGES_PER_CHUNK;
    for (int k = threadIdx.x; k < EDGES_PER_CHUNK; k += 256) {
        const int e = base + k;
        const int p = atomicAdd(&cur[dst[e]], 1);
        g_perm[p] = e;
    }
}

// ---------------- edge-parallel msg kernel (f32x2 packed) --------------------
// msg_e[o] = sum_i hin[src_e][i] * relu( sum_v ea[e][v]*We[v][i*COUT+o] + be[..] )
template <int CIN, int COUT, int COUTP>
__global__ __launch_bounds__(256) void msg_kernel(
    const float* __restrict__ ea,     // [E,6]
    const int*   __restrict__ srcv,   // [E]
    const float* __restrict__ We,     // [6, CIN*COUT]
    const float* __restrict__ be,     // [CIN*COUT]
    const float* __restrict__ hin)    // [N, CIN]
{
    static_assert(COUTP % 4 == 0, "pad");
    __shared__ __align__(16) float sWe[6 * CIN * COUTP];
    __shared__ __align__(16) float sBe[CIN * COUTP];

    const int tid = threadIdx.x;
    for (int t = tid; t < 6 * CIN * COUTP; t += 256) {
        int vi = t / COUTP, oc = t % COUTP;
        sWe[t] = (oc < COUT) ? We[vi * COUT + oc] : 0.f;
    }
    for (int t = tid; t < CIN * COUTP; t += 256) {
        int oc = t % COUTP;
        sBe[t] = (oc < COUT) ? be[(t / COUTP) * COUT + oc] : 0.f;
    }
    __syncthreads();

    const int e = blockIdx.x * 256 + tid;
    const float2* eap = (const float2*)(ea + (size_t)e * 6);
    const float2 ea0 = __ldg(eap + 0), ea1 = __ldg(eap + 1), ea2 = __ldg(eap + 2);
    uint64_t ap[6];
    ap[0] = f2pk(ea0.x, ea0.x); ap[1] = f2pk(ea0.y, ea0.y);
    ap[2] = f2pk(ea1.x, ea1.x); ap[3] = f2pk(ea1.y, ea1.y);
    ap[4] = f2pk(ea2.x, ea2.x); ap[5] = f2pk(ea2.y, ea2.y);
    const int s = __ldg(srcv + e);
    const float* xr = hin + s * CIN;

    uint64_t msg[COUTP / 2];
#pragma unroll
    for (int p = 0; p < COUTP / 2; p++) msg[p] = 0;

#pragma unroll 1   // keep i rolled: I$ discipline for CIN=36/24
    for (int i = 0; i < CIN; i++) {
        const float xi = __ldg(xr + i);
        const uint64_t xip = f2pk(xi, xi);
        const ulonglong2* w0 = (const ulonglong2*)(sWe + (0 * CIN + i) * COUTP);
        const ulonglong2* w1 = (const ulonglong2*)(sWe + (1 * CIN + i) * COUTP);
        const ulonglong2* w2 = (const ulonglong2*)(sWe + (2 * CIN + i) * COUTP);
        const ulonglong2* w3 = (const ulonglong2*)(sWe + (3 * CIN + i) * COUTP);
        const ulonglong2* w4 = (const ulonglong2*)(sWe + (4 * CIN + i) * COUTP);
        const ulonglong2* w5 = (const ulonglong2*)(sWe + (5 * CIN + i) * COUTP);
        const ulonglong2* bb = (const ulonglong2*)(sBe + i * COUTP);
#pragma unroll
        for (int c = 0; c < COUTP / 4; c++) {
            const ulonglong2 b  = bb[c];
            const ulonglong2 q0 = w0[c], q1 = w1[c], q2 = w2[c],
                             q3 = w3[c], q4 = w4[c], q5 = w5[c];
            uint64_t t0 = f2fma(ap[0], q0.x, b.x);
            t0 = f2fma(ap[1], q1.x, t0); t0 = f2fma(ap[2], q2.x, t0);
            t0 = f2fma(ap[3], q3.x, t0); t0 = f2fma(ap[4], q4.x, t0);
            t0 = f2fma(ap[5], q5.x, t0);
            uint64_t t1 = f2fma(ap[0], q0.y, b.y);
            t1 = f2fma(ap[1], q1.y, t1); t1 = f2fma(ap[2], q2.y, t1);
            t1 = f2fma(ap[3], q3.y, t1); t1 = f2fma(ap[4], q4.y, t1);
            t1 = f2fma(ap[5], q5.y, t1);
            t0 = f2relu(t0);
            t1 = f2relu(t1);
            msg[2 * c + 0] = f2fma(xip, t0, msg[2 * c + 0]);
            msg[2 * c + 1] = f2fma(xip, t1, msg[2 * c + 1]);
        }
    }

    ulonglong2* out = (ulonglong2*)(g_msg + (size_t)e * COUTP);
#pragma unroll
    for (int c = 0; c < COUTP / 4; c++) {
        ulonglong2 o; o.x = msg[2 * c]; o.y = msg[2 * c + 1];
        out[c] = o;
    }
}

// ---------------- CSR gather + finalize --------------------------------------
template <int CIN, int COUT, int COUTP>
__global__ __launch_bounds__(256) void gather_kernel(
    const float* __restrict__ root,   // [CIN, COUT]
    const float* __restrict__ bias,   // [COUT]
    const float* __restrict__ hin,    // [N, CIN]
    float*       __restrict__ hout)   // [N, COUT]
{
    __shared__ float sacc[COUTP];
    const int tid = threadIdx.x;
    if (tid < COUTP) sacc[tid] = 0.f;
    __syncthreads();

    const int d = blockIdx.x;
    float acc[COUTP];
#pragma unroll
    for (int o = 0; o < COUTP; o++) acc[o] = 0.f;

    const int start = g_ptr[d], finish = g_ptr[d + 1];
    for (int k = start + tid; k < finish; k += 256) {
        const int e = g_perm[k];
        const float4* m = (const float4*)(g_msg + (size_t)e * COUTP);
#pragma unroll
        for (int c = 0; c < COUTP / 4; c++) {
            const float4 v = __ldg(m + c);
            acc[4 * c + 0] += v.x; acc[4 * c + 1] += v.y;
            acc[4 * c + 2] += v.z; acc[4 * c + 3] += v.w;
        }
    }
#pragma unroll
    for (int o = 0; o < COUTP; o++) {
        float v = acc[o];
#pragma unroll
        for (int sh = 16; sh; sh >>= 1) v += __shfl_down_sync(0xffffffffu, v, sh);
        if ((tid & 31) == 0) atomicAdd(&sacc[o], v);
    }
    __syncthreads();

    if (tid < COUT) {
        float r = bias[tid];
#pragma unroll 1
        for (int i = 0; i < CIN; i++)
            r = fmaf(hin[d * CIN + i], root[i * COUT + tid], r);
        hout[d * COUT + tid] = fmaxf(fmaf(sacc[tid], g_invc[d], r), 0.f);
    }
}

// ---------------- CBT: out[i][j] = sum_k |h[i][k]-h[j][k]|, k<5 --------------
__global__ __launch_bounds__(256) void cbt_kernel(const float* __restrict__ h,
                                                  float* __restrict__ out) {
    __shared__ float sh[N_NODES * 5];
    for (int t = threadIdx.x; t < N_NODES * 5; t += 256) sh[t] = h[t];
    __syncthreads();
    const int i = blockIdx.x;
    const float h0 = sh[i * 5 + 0], h1 = sh[i * 5 + 1], h2 = sh[i * 5 + 2],
                h3 = sh[i * 5 + 3], h4 = sh[i * 5 + 4];
    for (int j = threadIdx.x; j < N_NODES; j += 256) {
        float s = fabsf(h0 - sh[j * 5 + 0]) + fabsf(h1 - sh[j * 5 + 1]) +
                  fabsf(h2 - sh[j * 5 + 2]) + fabsf(h3 - sh[j * 5 + 3]) +
                  fabsf(h4 - sh[j * 5 + 4]);
        out[i * N_NODES + j] = s;
    }
}

// ---------------- launch ------------------------------------------------------
extern "C" void kernel_launch(void* const* d_in, const int* in_sizes, int n_in,
                              void* d_out, int out_size) {
    const float* x    = (const float*)d_in[0];
    const float* ea   = (const float*)d_in[1];
    const int*   ei   = (const int*)d_in[2];
    const float* We1  = (const float*)d_in[3];
    const float* be1  = (const float*)d_in[4];
    const float* root1= (const float*)d_in[5];
    const float* b1   = (const float*)d_in[6];
    const float* We2  = (const float*)d_in[7];
    const float* be2  = (const float*)d_in[8];
    const float* root2= (const float*)d_in[9];
    const float* b2   = (const float*)d_in[10];
    const float* We3  = (const float*)d_in[11];
    const float* be3  = (const float*)d_in[12];
    const float* root3= (const float*)d_in[13];
    const float* b3   = (const float*)d_in[14];
    float* out = (float*)d_out;

    const int* src = ei;
    const int* dst = ei + N_EDGES;

    float* hA = nullptr;
    float* hB = nullptr;
    cudaGetSymbolAddress((void**)&hA, g_bufA);
    cudaGetSymbolAddress((void**)&hB, g_bufB);

    // CSR build: smem histograms -> single-CTA plan -> smem-cursor scatter
    count_kernel<<<CHUNKS, 256>>>(dst);
    plan_kernel<<<1, N_NODES>>>();
    scatter_kernel<<<CHUNKS, 256>>>(dst);

    // layer 1: 1 -> 36
    msg_kernel<1, 36, 36><<<N_EDGES / 256, 256>>>(ea, src, We1, be1, x);
    gather_kernel<1, 36, 36><<<N_NODES, 256>>>(root1, b1, x, hA);

    // layer 2: 36 -> 24
    msg_kernel<36, 24, 24><<<N_EDGES / 256, 256>>>(ea, src, We2, be2, hA);
    gather_kernel<36, 24, 24><<<N_NODES, 256>>>(root2, b2, hA, hB);

    // layer 3: 24 -> 5 (padded to 8)
    msg_kernel<24, 5, 8><<<N_EDGES / 256, 256>>>(ea, src, We3, be3, hB);
    gather_kernel<24, 5, 8><<<N_NODES, 256>>>(root3, b3, hB, hA);

    cbt_kernel<<<N_NODES, 256>>>(hA, out);
}

// round 4
// speedup vs baseline: 1.5204x; 1.0209x over previous
#include <cuda_runtime.h>
#include <cstdint>

#define N_NODES 512
#define N_EDGES (512 * 512)
#define CHUNKS 128
#define EDGES_PER_CHUNK (N_EDGES / CHUNKS)   // 2048

// ---------------- persistent device scratch (no allocations allowed) ---------
__device__ int   g_ptr[N_NODES + 1];
__device__ float g_invc[N_NODES];
__device__ int   g_counts[CHUNKS * N_NODES];
__device__ int   g_base[CHUNKS * N_NODES];
__device__ int   g_srcs[N_EDGES];                       // src, dst-sorted order
__device__ __align__(16) float g_eas[(size_t)N_EDGES * 8];  // ea rows, padded to 32B
__device__ float g_bufA[N_NODES * 36];
__device__ float g_bufB[N_NODES * 36];

// ---------------- f32x2 packed helpers ---------------------------------------
__device__ __forceinline__ uint64_t f2pk(float lo, float hi) {
    uint64_t r; asm("mov.b64 %0, {%1,%2};" : "=l"(r) : "f"(lo), "f"(hi)); return r;
}
__device__ __forceinline__ void f2upk(uint64_t v, float& lo, float& hi) {
    asm("mov.b64 {%0,%1}, %2;" : "=f"(lo), "=f"(hi) : "l"(v));
}
__device__ __forceinline__ uint64_t f2fma(uint64_t a, uint64_t b, uint64_t c) {
    uint64_t d; asm("fma.rn.f32x2 %0, %1, %2, %3;" : "=l"(d) : "l"(a), "l"(b), "l"(c));
    return d;
}
__device__ __forceinline__ uint64_t f2relu(uint64_t v) {
    float lo, hi; f2upk(v, lo, hi);
    return f2pk(fmaxf(lo, 0.f), fmaxf(hi, 0.f));
}

// ---------------- CSR build (atomic-free in gmem) ----------------------------
__global__ __launch_bounds__(256) void count_kernel(const int* __restrict__ dst) {
    __shared__ int h[N_NODES];
    for (int n = threadIdx.x; n < N_NODES; n += 256) h[n] = 0;
    __syncthreads();
    const int base = blockIdx.x * EDGES_PER_CHUNK;
    for (int k = threadIdx.x; k < EDGES_PER_CHUNK; k += 256)
        atomicAdd(&h[dst[base + k]], 1);
    __syncthreads();
    for (int n = threadIdx.x; n < N_NODES; n += 256)
        g_counts[blockIdx.x * N_NODES + n] = h[n];
}

__global__ __launch_bounds__(N_NODES) void plan_kernel() {
    __shared__ int s[N_NODES];
    const int t = threadIdx.x;
    int cnt = 0;
#pragma unroll 4
    for (int c = 0; c < CHUNKS; c++) cnt += g_counts[c * N_NODES + t];
    s[t] = cnt;
    __syncthreads();
    for (int off = 1; off < N_NODES; off <<= 1) {
        int v = (t >= off) ? s[t - off] : 0;
        __syncthreads();
        s[t] += v;
        __syncthreads();
    }
    const int incl = s[t];
    g_ptr[t + 1] = incl;
    if (t == 0) g_ptr[0] = 0;
    g_invc[t] = 1.0f / (float)max(cnt, 1);
    int run = incl - cnt;
#pragma unroll 4
    for (int c = 0; c < CHUNKS; c++) {
        int v = g_counts[c * N_NODES + t];
        g_base[c * N_NODES + t] = run;
        run += v;
    }
}

// scatter: permute edge data into dst-sorted order (smem cursors, no gmem atomics)
__global__ __launch_bounds__(256) void scatter_kernel(const int* __restrict__ srcv,
                                                      const int* __restrict__ dst,
                                                      const float* __restrict__ ea) {
    __shared__ int cur[N_NODES];
    for (int n = threadIdx.x; n < N_NODES; n += 256)
        cur[n] = g_base[blockIdx.x * N_NODES + n];
    __syncthreads();
    const int base = blockIdx.x * EDGES_PER_CHUNK;
    for (int k = threadIdx.x; k < EDGES_PER_CHUNK; k += 256) {
        const int e = base + k;
        const int p = atomicAdd(&cur[dst[e]], 1);
        g_srcs[p] = srcv[e];
        const float2* er = (const float2*)(ea + (size_t)e * 6);
        const float2 e0 = __ldg(er + 0), e1 = __ldg(er + 1), e2 = __ldg(er + 2);
        float4* w = (float4*)(g_eas + (size_t)p * 8);
        w[0] = make_float4(e0.x, e0.y, e1.x, e1.y);
        w[1] = make_float4(e2.x, e2.y, 0.f, 0.f);
    }
}

// ---------------- fused NNConv layer: one CTA per dst node -------------------
// msg_e[o] = sum_i hin[src_e][i] * relu( sum_v ea[e][v]*We[v][i*COUT+o] + be[..] )
// hout[d]  = relu( mean_e(msg) + hin[d] @ root + bias )
template <int CIN, int COUT, int COUTP>
__global__ __launch_bounds__(128) void fused_layer(
    const float* __restrict__ We,     // [6, CIN*COUT]
    const float* __restrict__ be,     // [CIN*COUT]
    const float* __restrict__ root,   // [CIN, COUT]
    const float* __restrict__ bias,   // [COUT]
    const float* __restrict__ hin,    // [N, CIN]
    float*       __restrict__ hout)   // [N, COUT]
{
    static_assert(COUTP % 4 == 0, "pad");
    __shared__ __align__(16) float sWe[6 * CIN * COUTP];
    __shared__ __align__(16) float sBe[CIN * COUTP];
    __shared__ float sacc[COUTP];

    const int tid = threadIdx.x;
    for (int t = tid; t < 6 * CIN * COUTP; t += 128) {
        int vi = t / COUTP, oc = t % COUTP;
        sWe[t] = (oc < COUT) ? We[vi * COUT + oc] : 0.f;
    }
    for (int t = tid; t < CIN * COUTP; t += 128) {
        int oc = t % COUTP;
        sBe[t] = (oc < COUT) ? be[(t / COUTP) * COUT + oc] : 0.f;
    }
    if (tid < COUTP) sacc[tid] = 0.f;
    __syncthreads();

    const int d = blockIdx.x;
    uint64_t msg[COUTP / 2];
#pragma unroll
    for (int p = 0; p < COUTP / 2; p++) msg[p] = 0;

    const int start = g_ptr[d], finish = g_ptr[d + 1];
    for (int k = start + tid; k < finish; k += 128) {
        const float4 e0 = __ldg((const float4*)(g_eas + (size_t)k * 8));
        const float2 e1 = __ldg((const float2*)(g_eas + (size_t)k * 8 + 4));
        uint64_t ap[6];
        ap[0] = f2pk(e0.x, e0.x); ap[1] = f2pk(e0.y, e0.y);
        ap[2] = f2pk(e0.z, e0.z); ap[3] = f2pk(e0.w, e0.w);
        ap[4] = f2pk(e1.x, e1.x); ap[5] = f2pk(e1.y, e1.y);
        const int s = __ldg(g_srcs + k);
        const float* xr = hin + s * CIN;

#pragma unroll 1   // keep i rolled: I$ discipline for CIN=36/24
        for (int i = 0; i < CIN; i++) {
            const float xi = __ldg(xr + i);
            const uint64_t xip = f2pk(xi, xi);
            const ulonglong2* w0 = (const ulonglong2*)(sWe + (0 * CIN + i) * COUTP);
            const ulonglong2* w1 = (const ulonglong2*)(sWe + (1 * CIN + i) * COUTP);
            const ulonglong2* w2 = (const ulonglong2*)(sWe + (2 * CIN + i) * COUTP);
            const ulonglong2* w3 = (const ulonglong2*)(sWe + (3 * CIN + i) * COUTP);
            const ulonglong2* w4 = (const ulonglong2*)(sWe + (4 * CIN + i) * COUTP);
            const ulonglong2* w5 = (const ulonglong2*)(sWe + (5 * CIN + i) * COUTP);
            const ulonglong2* bb = (const ulonglong2*)(sBe + i * COUTP);
#pragma unroll
            for (int c = 0; c < COUTP / 4; c++) {
                const ulonglong2 b  = bb[c];
                const ulonglong2 q0 = w0[c], q1 = w1[c], q2 = w2[c],
                                 q3 = w3[c], q4 = w4[c], q5 = w5[c];
                uint64_t t0 = f2fma(ap[0], q0.x, b.x);
                t0 = f2fma(ap[1], q1.x, t0); t0 = f2fma(ap[2], q2.x, t0);
                t0 = f2fma(ap[3], q3.x, t0); t0 = f2fma(ap[4], q4.x, t0);
                t0 = f2fma(ap[5], q5.x, t0);
                uint64_t t1 = f2fma(ap[0], q0.y, b.y);
                t1 = f2fma(ap[1], q1.y, t1); t1 = f2fma(ap[2], q2.y, t1);
                t1 = f2fma(ap[3], q3.y, t1); t1 = f2fma(ap[4], q4.y, t1);
                t1 = f2fma(ap[5], q5.y, t1);
                t0 = f2relu(t0);
                t1 = f2relu(t1);
                msg[2 * c + 0] = f2fma(xip, t0, msg[2 * c + 0]);
                msg[2 * c + 1] = f2fma(xip, t1, msg[2 * c + 1]);
            }
        }
    }

    // block reduction: warp shfl -> smem atomics
#pragma unroll
    for (int p = 0; p < COUTP / 2; p++) {
        float lo, hi; f2upk(msg[p], lo, hi);
#pragma unroll
        for (int sh = 16; sh; sh >>= 1) {
            lo += __shfl_down_sync(0xffffffffu, lo, sh);
            hi += __shfl_down_sync(0xffffffffu, hi, sh);
        }
        if ((tid & 31) == 0) {
            atomicAdd(&sacc[2 * p + 0], lo);
            atomicAdd(&sacc[2 * p + 1], hi);
        }
    }
    __syncthreads();

    if (tid < COUT) {
        float r = bias[tid];
#pragma unroll 1
        for (int i = 0; i < CIN; i++)
            r = fmaf(hin[d * CIN + i], root[i * COUT + tid], r);
        hout[d * COUT + tid] = fmaxf(fmaf(sacc[tid], g_invc[d], r), 0.f);
    }
}

// ---------------- CBT: out[i][j] = sum_k |h[i][k]-h[j][k]|, k<5 --------------
__global__ __launch_bounds__(256) void cbt_kernel(const float* __restrict__ h,
                                                  float* __restrict__ out) {
    __shared__ float sh[N_NODES * 5];
    for (int t = threadIdx.x; t < N_NODES * 5; t += 256) sh[t] = h[t];
    __syncthreads();
    const int i = blockIdx.x;
    const float h0 = sh[i * 5 + 0], h1 = sh[i * 5 + 1], h2 = sh[i * 5 + 2],
                h3 = sh[i * 5 + 3], h4 = sh[i * 5 + 4];
    for (int j = threadIdx.x; j < N_NODES; j += 256) {
        float s = fabsf(h0 - sh[j * 5 + 0]) + fabsf(h1 - sh[j * 5 + 1]) +
                  fabsf(h2 - sh[j * 5 + 2]) + fabsf(h3 - sh[j * 5 + 3]) +
                  fabsf(h4 - sh[j * 5 + 4]);
        out[i * N_NODES + j] = s;
    }
}

// ---------------- launch ------------------------------------------------------
extern "C" void kernel_launch(void* const* d_in, const int* in_sizes, int n_in,
                              void* d_out, int out_size) {
    const float* x    = (const float*)d_in[0];
    const float* ea   = (const float*)d_in[1];
    const int*   ei   = (const int*)d_in[2];
    const float* We1  = (const float*)d_in[3];
    const float* be1  = (const float*)d_in[4];
    const float* root1= (const float*)d_in[5];
    const float* b1   = (const float*)d_in[6];
    const float* We2  = (const float*)d_in[7];
    const float* be2  = (const float*)d_in[8];
    const float* root2= (const float*)d_in[9];
    const float* b2   = (const float*)d_in[10];
    const float* We3  = (const float*)d_in[11];
    const float* be3  = (const float*)d_in[12];
    const float* root3= (const float*)d_in[13];
    const float* b3   = (const float*)d_in[14];
    float* out = (float*)d_out;

    const int* src = ei;
    const int* dst = ei + N_EDGES;

    float* hA = nullptr;
    float* hB = nullptr;
    cudaGetSymbolAddress((void**)&hA, g_bufA);
    cudaGetSymbolAddress((void**)&hB, g_bufB);

    // CSR build + edge-data permute into dst-sorted order
    count_kernel<<<CHUNKS, 256>>>(dst);
    plan_kernel<<<1, N_NODES>>>();
    scatter_kernel<<<CHUNKS, 256>>>(src, dst, ea);

    // fused NNConv layers (no msg round-trip through gmem)
    fused_layer<1, 36, 36><<<N_NODES, 128>>>(We1, be1, root1, b1, x,  hA);
    fused_layer<36, 24, 24><<<N_NODES, 128>>>(We2, be2, root2, b2, hA, hB);
    fused_layer<24, 5, 8><<<N_NODES, 128>>>(We3, be3, root3, b3, hB, hA);

    cbt_kernel<<<N_NODES, 256>>>(hA, out);
}